// round 1
// baseline (speedup 1.0000x reference)
#include <cuda_runtime.h>
#include <math.h>
#include <stdint.h>

#define B_ 256
#define F_ 128
#define D_ 512
#define H_ 8
#define HD_ 64
#define KVAL_ 64

// ---------------- scratch (no allocations allowed) ----------------
__device__ float g_q[(size_t)B_ * H_ * F_ * HD_];
__device__ float g_k[(size_t)B_ * H_ * F_ * HD_];
__device__ float g_v[(size_t)B_ * H_ * F_ * HD_];
__device__ float g_attn[(size_t)B_ * F_ * D_];
__device__ float g_pv[B_];

// ---------------- kernel 1: gate scalar pv[b] ----------------
__global__ void pv_kernel(const float* __restrict__ x,
                          const float* __restrict__ W1,
                          const float* __restrict__ b1,
                          const float* __restrict__ W2,
                          const float* __restrict__ b2) {
    __shared__ float comb[2 * D_];
    __shared__ float hbuf[D_];
    __shared__ float red[256];
    int b = blockIdx.x, t = threadIdx.x;
    const float* xb = x + (size_t)b * F_ * D_;

    for (int d = t; d < D_; d += 256) {
        float sp = 0.f, sv = 0.f;
        for (int f = 0; f < F_ / 2; ++f)       sp += xb[f * D_ + d];
        for (int f = F_ / 2; f < F_; ++f)      sv += xb[f * D_ + d];
        comb[d]       = sp * (2.0f / F_);
        comb[D_ + d]  = sv * (2.0f / F_);
    }
    __syncthreads();

    for (int j = t; j < D_; j += 256) {
        float acc = b1[j];
        for (int i = 0; i < 2 * D_; ++i) acc += comb[i] * W1[i * D_ + j];
        hbuf[j] = acc / (1.0f + expf(-acc));   // silu
    }
    __syncthreads();

    float part = 0.f;
    for (int j = t; j < D_; j += 256) part += hbuf[j] * W2[j];
    red[t] = part;
    __syncthreads();
    for (int s = 128; s > 0; s >>= 1) {
        if (t < s) red[t] += red[t + s];
        __syncthreads();
    }
    if (t == 0) {
        float z = red[0] + b2[0];
        g_pv[b] = 1.0f / (1.0f + expf(-z));
    }
}

// ---------------- kernel 2: tiled SGEMM, M x 512 @ 512 x 512 + bias ----------------
// HEAD_LAYOUT: write C as (b, h, f, hd); else plain row-major (m, n).
template <bool HEAD_LAYOUT>
__global__ void sgemm512(const float* __restrict__ A,
                         const float* __restrict__ W,
                         const float* __restrict__ bias,
                         float* __restrict__ C) {
    __shared__ float As[16][68];   // transposed A tile: As[k][m], padded
    __shared__ float Bs[16][64];

    const int m0 = blockIdx.x * 64;
    const int n0 = blockIdx.y * 64;
    const int t  = threadIdx.x;
    const int tr = t >> 4;          // 0..15 (row tile)
    const int tc = t & 15;          // 0..15 (col tile)

    float acc[4][4] = {};

    for (int kt = 0; kt < 512; kt += 16) {
        {
            int row = t >> 2;               // 0..63
            int c4  = (t & 3) * 4;          // 0,4,8,12
            float4 a = *(const float4*)(A + (size_t)(m0 + row) * 512 + kt + c4);
            As[c4 + 0][row] = a.x;
            As[c4 + 1][row] = a.y;
            As[c4 + 2][row] = a.z;
            As[c4 + 3][row] = a.w;
            int rr = t >> 4;                // 0..15
            int cc = (t & 15) * 4;
            *(float4*)(&Bs[rr][cc]) =
                *(const float4*)(W + (size_t)(kt + rr) * 512 + n0 + cc);
        }
        __syncthreads();
#pragma unroll
        for (int k = 0; k < 16; ++k) {
            float4 a = *(const float4*)(&As[k][tr * 4]);
            float4 bb = *(const float4*)(&Bs[k][tc * 4]);
            acc[0][0] += a.x * bb.x; acc[0][1] += a.x * bb.y;
            acc[0][2] += a.x * bb.z; acc[0][3] += a.x * bb.w;
            acc[1][0] += a.y * bb.x; acc[1][1] += a.y * bb.y;
            acc[1][2] += a.y * bb.z; acc[1][3] += a.y * bb.w;
            acc[2][0] += a.z * bb.x; acc[2][1] += a.z * bb.y;
            acc[2][2] += a.z * bb.z; acc[2][3] += a.z * bb.w;
            acc[3][0] += a.w * bb.x; acc[3][1] += a.w * bb.y;
            acc[3][2] += a.w * bb.z; acc[3][3] += a.w * bb.w;
        }
        __syncthreads();
    }

    float4 bb = *(const float4*)(bias + n0 + tc * 4);
#pragma unroll
    for (int i = 0; i < 4; ++i) {
        int m = m0 + tr * 4 + i;
        float4 r;
        r.x = acc[i][0] + bb.x;
        r.y = acc[i][1] + bb.y;
        r.z = acc[i][2] + bb.z;
        r.w = acc[i][3] + bb.w;
        if (HEAD_LAYOUT) {
            int b  = m >> 7;         // m / F_
            int f  = m & (F_ - 1);
            int n  = n0 + tc * 4;
            int h  = n >> 6;         // n / HD_
            int hd = n & (HD_ - 1);
            *(float4*)(C + ((((size_t)b * H_ + h) * F_ + f) * HD_ + hd)) = r;
        } else {
            *(float4*)(C + (size_t)m * 512 + n0 + tc * 4) = r;
        }
    }
}

// ---------------- kernel 3: fused attention per (b, h) ----------------
struct AttnSmem {
    float Qt[HD_][F_];      // [hd][f]
    float Kt[HD_][F_];      // [hd][f]
    float V[F_][HD_];       // [k][hd]
    float S[F_][F_ + 1];    // scores / attn, padded stride 129
    float fi[F_];
};

__global__ void attn_kernel(const float* __restrict__ corr,
                            const float* __restrict__ fi_g,
                            float* __restrict__ out_attn) {
    extern __shared__ char smem_raw[];
    AttnSmem& sm = *reinterpret_cast<AttnSmem*>(smem_raw);

    const int bh = blockIdx.x;
    const int b  = bh >> 3;
    const int h  = bh & 7;
    const int t  = threadIdx.x;

    const float4* qg = (const float4*)(g_q + (size_t)bh * F_ * HD_);
    const float4* kg = (const float4*)(g_k + (size_t)bh * F_ * HD_);
    const float4* vg = (const float4*)(g_v + (size_t)bh * F_ * HD_);

    for (int i = t; i < F_ * HD_ / 4; i += 256) {
        float4 q4 = qg[i];
        float4 k4 = kg[i];
        float4 v4 = vg[i];
        int f  = i >> 4;            // 16 float4 per row of 64
        int hd = (i & 15) << 2;
        sm.Qt[hd + 0][f] = q4.x; sm.Qt[hd + 1][f] = q4.y;
        sm.Qt[hd + 2][f] = q4.z; sm.Qt[hd + 3][f] = q4.w;
        sm.Kt[hd + 0][f] = k4.x; sm.Kt[hd + 1][f] = k4.y;
        sm.Kt[hd + 2][f] = k4.z; sm.Kt[hd + 3][f] = k4.w;
        ((float4*)&sm.V[0][0])[i] = v4;
    }
    if (t < F_) sm.fi[t] = fi_g[t];
    __syncthreads();

    // ---- scores = Q K^T / 8 + prior + gate, 8x8 per thread ----
    {
        const int tr = t >> 4, tc = t & 15;
        const int q0 = tr * 8, k0 = tc * 8;
        float acc[8][8] = {};
#pragma unroll 4
        for (int hd = 0; hd < HD_; ++hd) {
            float4 qa = *(const float4*)&sm.Qt[hd][q0];
            float4 qb = *(const float4*)&sm.Qt[hd][q0 + 4];
            float4 ka = *(const float4*)&sm.Kt[hd][k0];
            float4 kb = *(const float4*)&sm.Kt[hd][k0 + 4];
            float qv[8] = {qa.x, qa.y, qa.z, qa.w, qb.x, qb.y, qb.z, qb.w};
            float kv[8] = {ka.x, ka.y, ka.z, ka.w, kb.x, kb.y, kb.z, kb.w};
#pragma unroll
            for (int i = 0; i < 8; ++i)
#pragma unroll
                for (int j = 0; j < 8; ++j) acc[i][j] += qv[i] * kv[j];
        }
        const float pvb = g_pv[b] * 0.5f;
#pragma unroll
        for (int i = 0; i < 8; ++i) {
            int fq = q0 + i;
            float fiq = sm.fi[fq];
            bool qlow = fq < (F_ / 2);
#pragma unroll
            for (int j = 0; j < 8; ++j) {
                int kk = k0 + j;
                float sc = acc[i][j] * 0.125f;    // 1/sqrt(64)
                sc += corr[fq * F_ + kk] * (fiq * sm.fi[kk]);
                if (qlow != (kk < (F_ / 2))) sc += pvb;
                sm.S[fq][kk] = sc;
            }
        }
    }
    __syncthreads();

    // ---- per-row exact 64th-largest threshold (radix select) + softmax ----
    {
        const int warp = t >> 5, lane = t & 31;
        for (int rr = 0; rr < 16; ++rr) {
            int row = warp * 16 + rr;
            float vals[4];
            unsigned keys[4];
#pragma unroll
            for (int i = 0; i < 4; ++i) {
                vals[i] = sm.S[row][lane + 32 * i];
                unsigned u = __float_as_uint(vals[i]);
                keys[i] = (u & 0x80000000u) ? ~u : (u | 0x80000000u);
            }
            unsigned prefix = 0;
            int r = KVAL_ - 1;     // rank 63 descending
#pragma unroll
            for (int bit = 31; bit >= 0; --bit) {
                unsigned test = prefix | (1u << bit);
                int loc = 0;
#pragma unroll
                for (int i = 0; i < 4; ++i)
                    loc += ((keys[i] >> bit) == (test >> bit));
                int cnt = __reduce_add_sync(0xffffffffu, loc);
                if (cnt > r) prefix = test; else r -= cnt;
            }
            // row max (top element survives masking, so max == kept max)
            float mx = fmaxf(fmaxf(vals[0], vals[1]), fmaxf(vals[2], vals[3]));
#pragma unroll
            for (int o = 16; o > 0; o >>= 1)
                mx = fmaxf(mx, __shfl_xor_sync(0xffffffffu, mx, o));
            float e[4];
            float sum = 0.f;
#pragma unroll
            for (int i = 0; i < 4; ++i) {
                e[i] = (keys[i] >= prefix) ? __expf(vals[i] - mx) : 0.f;
                sum += e[i];
            }
#pragma unroll
            for (int o = 16; o > 0; o >>= 1)
                sum += __shfl_xor_sync(0xffffffffu, sum, o);
            float inv = 1.0f / sum;
#pragma unroll
            for (int i = 0; i < 4; ++i)
                sm.S[row][lane + 32 * i] = e[i] * inv;
        }
    }
    __syncthreads();

    // ---- out = attn @ V : each thread = 1 query row x 32 dims ----
    {
        const int q  = t >> 1;
        const int d0 = (t & 1) * 32;
        float acc2[32] = {};
        for (int kk = 0; kk < F_; ++kk) {
            float a = sm.S[q][kk];
            const float* vrow = &sm.V[kk][d0];
#pragma unroll
            for (int dd = 0; dd < 32; dd += 4) {
                float4 vv = *(const float4*)(vrow + dd);
                acc2[dd + 0] += a * vv.x;
                acc2[dd + 1] += a * vv.y;
                acc2[dd + 2] += a * vv.z;
                acc2[dd + 3] += a * vv.w;
            }
        }
        float* og = out_attn + ((size_t)b * F_ + q) * D_ + h * HD_ + d0;
#pragma unroll
        for (int dd = 0; dd < 32; dd += 4) {
            float4 r = make_float4(acc2[dd], acc2[dd + 1], acc2[dd + 2], acc2[dd + 3]);
            *(float4*)(og + dd) = r;
        }
    }
}

// ---------------- host launcher ----------------
extern "C" void kernel_launch(void* const* d_in, const int* in_sizes, int n_in,
                              void* d_out, int out_size) {
    const float* x    = (const float*)d_in[0];
    const float* Wq   = (const float*)d_in[1];
    const float* bq   = (const float*)d_in[2];
    const float* Wk   = (const float*)d_in[3];
    const float* bk   = (const float*)d_in[4];
    const float* Wv   = (const float*)d_in[5];
    const float* bv   = (const float*)d_in[6];
    const float* Wo   = (const float*)d_in[7];
    const float* bo   = (const float*)d_in[8];
    const float* corr = (const float*)d_in[9];
    const float* fi   = (const float*)d_in[10];
    const float* W1   = (const float*)d_in[11];
    const float* b1   = (const float*)d_in[12];
    const float* W2   = (const float*)d_in[13];
    const float* b2   = (const float*)d_in[14];
    float* out = (float*)d_out;

    float *qp, *kp, *vp, *ap;
    cudaGetSymbolAddress((void**)&qp, g_q);
    cudaGetSymbolAddress((void**)&kp, g_k);
    cudaGetSymbolAddress((void**)&vp, g_v);
    cudaGetSymbolAddress((void**)&ap, g_attn);

    // 1. gate scalar
    pv_kernel<<<B_, 256>>>(x, W1, b1, W2, b2);

    // 2. Q/K/V projections (head-major outputs)
    dim3 gg(512, 8);   // M/64, N/64 for M = B*F = 32768, N = 512
    sgemm512<true><<<gg, 256>>>(x, Wq, bq, qp);
    sgemm512<true><<<gg, 256>>>(x, Wk, bk, kp);
    sgemm512<true><<<gg, 256>>>(x, Wv, bv, vp);

    // 3. fused attention
    cudaFuncSetAttribute(attn_kernel,
                         cudaFuncAttributeMaxDynamicSharedMemorySize,
                         (int)sizeof(AttnSmem));
    attn_kernel<<<B_ * H_, 256, sizeof(AttnSmem)>>>(corr, fi, ap);

    // 4. output projection -> d_out
    sgemm512<false><<<gg, 256>>>(ap, Wo, bo, out);
}

// round 7
// speedup vs baseline: 1.0172x; 1.0172x over previous
#include <cuda_runtime.h>
#include <math.h>
#include <stdint.h>

#define B_ 256
#define F_ 128
#define D_ 512
#define H_ 8
#define HD_ 64
#define KVAL_ 64

// ---------------- scratch (no allocations allowed) ----------------
__device__ float g_q[(size_t)B_ * H_ * F_ * HD_];
__device__ float g_k[(size_t)B_ * H_ * F_ * HD_];
__device__ float g_v[(size_t)B_ * H_ * F_ * HD_];
__device__ float g_attn[(size_t)B_ * F_ * D_];
__device__ float g_pv[B_];

// ---------------- kernel 1: gate scalar pv[b] ----------------
__global__ void pv_kernel(const float* __restrict__ x,
                          const float* __restrict__ W1,
                          const float* __restrict__ b1,
                          const float* __restrict__ W2,
                          const float* __restrict__ b2) {
    __shared__ float comb[2 * D_];
    __shared__ float hbuf[D_];
    __shared__ float red[256];
    int b = blockIdx.x, t = threadIdx.x;
    const float* xb = x + (size_t)b * F_ * D_;

    for (int d = t; d < D_; d += 256) {
        float sp = 0.f, sv = 0.f;
        for (int f = 0; f < F_ / 2; ++f)  sp += xb[f * D_ + d];
        for (int f = F_ / 2; f < F_; ++f) sv += xb[f * D_ + d];
        comb[d]      = sp * (2.0f / F_);
        comb[D_ + d] = sv * (2.0f / F_);
    }
    __syncthreads();

    for (int j = t; j < D_; j += 256) {
        float acc = b1[j];
        for (int i = 0; i < 2 * D_; ++i) acc += comb[i] * W1[i * D_ + j];
        hbuf[j] = acc / (1.0f + expf(-acc));
    }
    __syncthreads();

    float part = 0.f;
    for (int j = t; j < D_; j += 256) part += hbuf[j] * W2[j];
    red[t] = part;
    __syncthreads();
    for (int s = 128; s > 0; s >>= 1) {
        if (t < s) red[t] += red[t + s];
        __syncthreads();
    }
    if (t == 0) {
        float z = red[0] + b2[0];
        g_pv[b] = 1.0f / (1.0f + expf(-z));
    }
}

// ---------------- kernel 2: fp32 SIMT SGEMM (proven-exact path) ----------------
// C[M x 512] = A[M x 512] @ W[512 x 512] + bias.
// Tile 128x128, BK=16, 256 threads, 8x8 per thread (16x16 thread grid).
// Same algorithm as the round-1 validated kernel, scaled up for FMA ratio.
template <bool HEAD_LAYOUT>
__global__ __launch_bounds__(256)
void sgemm_f32(const float* __restrict__ A,
               const float* __restrict__ W,
               const float* __restrict__ bias,
               float* __restrict__ C) {
    __shared__ float As[16][132];   // transposed A tile: As[k][m], padded
    __shared__ float Bs[16][128];   // Bs[k][n]

    const int m0 = blockIdx.x * 128;
    const int n0 = blockIdx.y * 128;
    const int t  = threadIdx.x;
    const int tr = t >> 4;          // 0..15 -> rows tr*8..tr*8+7
    const int tc = t & 15;          // 0..15 -> cols tc*8..tc*8+7

    float acc[8][8] = {};

    for (int kt = 0; kt < 512; kt += 16) {
#pragma unroll
        for (int j = 0; j < 2; ++j) {
            int id  = j * 256 + t;
            // A tile: 128 rows x 16 k  (512 float4)
            int row = id >> 2;
            int c4  = (id & 3) * 4;
            float4 a = *(const float4*)(A + (size_t)(m0 + row) * 512 + kt + c4);
            As[c4 + 0][row] = a.x;
            As[c4 + 1][row] = a.y;
            As[c4 + 2][row] = a.z;
            As[c4 + 3][row] = a.w;
            // B tile: 16 k x 128 n  (512 float4)
            int kr = id >> 5;
            int cc = (id & 31) * 4;
            *(float4*)(&Bs[kr][cc]) =
                *(const float4*)(W + (size_t)(kt + kr) * 512 + n0 + cc);
        }
        __syncthreads();

#pragma unroll
        for (int k = 0; k < 16; ++k) {
            float av[8], bv[8];
            *(float4*)(av)     = *(const float4*)&As[k][tr * 8];
            *(float4*)(av + 4) = *(const float4*)&As[k][tr * 8 + 4];
            *(float4*)(bv)     = *(const float4*)&Bs[k][tc * 8];
            *(float4*)(bv + 4) = *(const float4*)&Bs[k][tc * 8 + 4];
#pragma unroll
            for (int i = 0; i < 8; ++i)
#pragma unroll
                for (int j = 0; j < 8; ++j) acc[i][j] += av[i] * bv[j];
        }
        __syncthreads();
    }

    // epilogue: + bias, write 8x8
    const int nb = n0 + tc * 8;
    float bv[8];
    *(float4*)(bv)     = *(const float4*)(bias + nb);
    *(float4*)(bv + 4) = *(const float4*)(bias + nb + 4);
#pragma unroll
    for (int i = 0; i < 8; ++i) {
        int m = m0 + tr * 8 + i;
        float4 r0 = make_float4(acc[i][0] + bv[0], acc[i][1] + bv[1],
                                acc[i][2] + bv[2], acc[i][3] + bv[3]);
        float4 r1 = make_float4(acc[i][4] + bv[4], acc[i][5] + bv[5],
                                acc[i][6] + bv[6], acc[i][7] + bv[7]);
        if (HEAD_LAYOUT) {
            int b  = m >> 7;          // m / F_
            int f  = m & (F_ - 1);
            int h  = nb >> 6;         // 8-col group never straddles a head
            int hd = nb & (HD_ - 1);
            size_t base = (((size_t)b * H_ + h) * F_ + f) * HD_ + hd;
            *(float4*)(C + base)     = r0;
            *(float4*)(C + base + 4) = r1;
        } else {
            *(float4*)(C + (size_t)m * 512 + nb)     = r0;
            *(float4*)(C + (size_t)m * 512 + nb + 4) = r1;
        }
    }
}

// ---------------- kernel 3: fused attention per (b, h) ----------------
struct AttnSmem {
    float Qt[HD_][F_];      // [hd][f]
    float Kt[HD_][F_];      // [hd][f]
    float V[F_][HD_];       // [k][hd]
    float S[F_][F_ + 1];    // scores / attn, padded stride 129
    float fi[F_];
};

__global__ void attn_kernel(const float* __restrict__ corr,
                            const float* __restrict__ fi_g,
                            float* __restrict__ out_attn) {
    extern __shared__ char smem_raw[];
    AttnSmem& sm = *reinterpret_cast<AttnSmem*>(smem_raw);

    const int bh = blockIdx.x;
    const int b  = bh >> 3;
    const int h  = bh & 7;
    const int t  = threadIdx.x;

    const float4* qg = (const float4*)(g_q + (size_t)bh * F_ * HD_);
    const float4* kg = (const float4*)(g_k + (size_t)bh * F_ * HD_);
    const float4* vg = (const float4*)(g_v + (size_t)bh * F_ * HD_);

    for (int i = t; i < F_ * HD_ / 4; i += 256) {
        float4 q4 = qg[i];
        float4 k4 = kg[i];
        float4 v4 = vg[i];
        int f  = i >> 4;
        int hd = (i & 15) << 2;
        sm.Qt[hd + 0][f] = q4.x; sm.Qt[hd + 1][f] = q4.y;
        sm.Qt[hd + 2][f] = q4.z; sm.Qt[hd + 3][f] = q4.w;
        sm.Kt[hd + 0][f] = k4.x; sm.Kt[hd + 1][f] = k4.y;
        sm.Kt[hd + 2][f] = k4.z; sm.Kt[hd + 3][f] = k4.w;
        ((float4*)&sm.V[0][0])[i] = v4;
    }
    if (t < F_) sm.fi[t] = fi_g[t];
    __syncthreads();

    // ---- scores = Q K^T / 8 + prior + gate, 8x8 per thread ----
    {
        const int tr = t >> 4, tc = t & 15;
        const int q0 = tr * 8, k0 = tc * 8;
        float acc[8][8] = {};
#pragma unroll 4
        for (int hd = 0; hd < HD_; ++hd) {
            float4 qa = *(const float4*)&sm.Qt[hd][q0];
            float4 qb = *(const float4*)&sm.Qt[hd][q0 + 4];
            float4 ka = *(const float4*)&sm.Kt[hd][k0];
            float4 kb = *(const float4*)&sm.Kt[hd][k0 + 4];
            float qv[8] = {qa.x, qa.y, qa.z, qa.w, qb.x, qb.y, qb.z, qb.w};
            float kv[8] = {ka.x, ka.y, ka.z, ka.w, kb.x, kb.y, kb.z, kb.w};
#pragma unroll
            for (int i = 0; i < 8; ++i)
#pragma unroll
                for (int j = 0; j < 8; ++j) acc[i][j] += qv[i] * kv[j];
        }
        const float pvb = g_pv[b] * 0.5f;
#pragma unroll
        for (int i = 0; i < 8; ++i) {
            int fq = q0 + i;
            float fiq = sm.fi[fq];
            bool qlow = fq < (F_ / 2);
#pragma unroll
            for (int j = 0; j < 8; ++j) {
                int kk = k0 + j;
                float sc = acc[i][j] * 0.125f;
                sc += corr[fq * F_ + kk] * (fiq * sm.fi[kk]);
                if (qlow != (kk < (F_ / 2))) sc += pvb;
                sm.S[fq][kk] = sc;
            }
        }
    }
    __syncthreads();

    // ---- per-row exact 64th-largest threshold + softmax, ILP=4 rows ----
    {
        const int warp = t >> 5, lane = t & 31;
#pragma unroll
        for (int grp = 0; grp < 4; ++grp) {
            int row0 = warp * 16 + grp * 4;
            float vals[4][4];
            unsigned keys[4][4];
#pragma unroll
            for (int rr = 0; rr < 4; ++rr)
#pragma unroll
                for (int i = 0; i < 4; ++i) {
                    float v = sm.S[row0 + rr][lane + 32 * i];
                    vals[rr][i] = v;
                    unsigned u = __float_as_uint(v);
                    keys[rr][i] = (u & 0x80000000u) ? ~u : (u | 0x80000000u);
                }
            unsigned prefix[4] = {0, 0, 0, 0};
            int r[4] = {KVAL_ - 1, KVAL_ - 1, KVAL_ - 1, KVAL_ - 1};
#pragma unroll
            for (int bit = 31; bit >= 0; --bit) {
                int cnt[4];
#pragma unroll
                for (int rr = 0; rr < 4; ++rr) {
                    unsigned test = prefix[rr] | (1u << bit);
                    int loc = 0;
#pragma unroll
                    for (int i = 0; i < 4; ++i)
                        loc += ((keys[rr][i] >> bit) == (test >> bit));
                    cnt[rr] = __reduce_add_sync(0xffffffffu, loc);
                }
#pragma unroll
                for (int rr = 0; rr < 4; ++rr) {
                    unsigned test = prefix[rr] | (1u << bit);
                    if (cnt[rr] > r[rr]) prefix[rr] = test;
                    else                 r[rr] -= cnt[rr];
                }
            }
#pragma unroll
            for (int rr = 0; rr < 4; ++rr) {
                float mx = fmaxf(fmaxf(vals[rr][0], vals[rr][1]),
                                 fmaxf(vals[rr][2], vals[rr][3]));
#pragma unroll
                for (int o = 16; o > 0; o >>= 1)
                    mx = fmaxf(mx, __shfl_xor_sync(0xffffffffu, mx, o));
                float e[4];
                float sum = 0.f;
#pragma unroll
                for (int i = 0; i < 4; ++i) {
                    e[i] = (keys[rr][i] >= prefix[rr]) ? __expf(vals[rr][i] - mx) : 0.f;
                    sum += e[i];
                }
#pragma unroll
                for (int o = 16; o > 0; o >>= 1)
                    sum += __shfl_xor_sync(0xffffffffu, sum, o);
                float inv = 1.0f / sum;
#pragma unroll
                for (int i = 0; i < 4; ++i)
                    sm.S[row0 + rr][lane + 32 * i] = e[i] * inv;
            }
        }
    }
    __syncthreads();

    // ---- out = attn @ V : register outer product, 4 q x 8 d per thread ----
    {
        const int qg2 = t >> 3;           // 0..31 -> rows qg2*4 .. +3
        const int d0  = (t & 7) * 8;      // 0..56
        float acc2[4][8] = {};
        for (int kk = 0; kk < F_; ++kk) {
            float4 va = *(const float4*)&sm.V[kk][d0];
            float4 vb = *(const float4*)&sm.V[kk][d0 + 4];
            float vv[8] = {va.x, va.y, va.z, va.w, vb.x, vb.y, vb.z, vb.w};
#pragma unroll
            for (int i = 0; i < 4; ++i) {
                float s = sm.S[qg2 * 4 + i][kk];
#pragma unroll
                for (int j = 0; j < 8; ++j) acc2[i][j] += s * vv[j];
            }
        }
#pragma unroll
        for (int i = 0; i < 4; ++i) {
            int qrow = qg2 * 4 + i;
            float* og = out_attn + ((size_t)b * F_ + qrow) * D_ + h * HD_ + d0;
            *(float4*)(og)     = make_float4(acc2[i][0], acc2[i][1], acc2[i][2], acc2[i][3]);
            *(float4*)(og + 4) = make_float4(acc2[i][4], acc2[i][5], acc2[i][6], acc2[i][7]);
        }
    }
}

// ---------------- host launcher ----------------
extern "C" void kernel_launch(void* const* d_in, const int* in_sizes, int n_in,
                              void* d_out, int out_size) {
    const float* x    = (const float*)d_in[0];
    const float* Wq   = (const float*)d_in[1];
    const float* bq   = (const float*)d_in[2];
    const float* Wk   = (const float*)d_in[3];
    const float* bk   = (const float*)d_in[4];
    const float* Wv   = (const float*)d_in[5];
    const float* bv   = (const float*)d_in[6];
    const float* Wo   = (const float*)d_in[7];
    const float* bo   = (const float*)d_in[8];
    const float* corr = (const float*)d_in[9];
    const float* fi   = (const float*)d_in[10];
    const float* W1   = (const float*)d_in[11];
    const float* b1   = (const float*)d_in[12];
    const float* W2   = (const float*)d_in[13];
    const float* b2   = (const float*)d_in[14];
    float* out = (float*)d_out;

    float *qp, *kp, *vp, *ap;
    cudaGetSymbolAddress((void**)&qp, g_q);
    cudaGetSymbolAddress((void**)&kp, g_k);
    cudaGetSymbolAddress((void**)&vp, g_v);
    cudaGetSymbolAddress((void**)&ap, g_attn);

    cudaFuncSetAttribute(attn_kernel,
                         cudaFuncAttributeMaxDynamicSharedMemorySize,
                         (int)sizeof(AttnSmem));

    // 1. gate scalar
    pv_kernel<<<B_, 256>>>(x, W1, b1, W2, b2);

    // 2. Q/K/V projections (head-major outputs), pure fp32
    dim3 gg(256, 4);   // M/128 = 32768/128, N/128 = 4
    sgemm_f32<true><<<gg, 256>>>(x, Wq, bq, qp);
    sgemm_f32<true><<<gg, 256>>>(x, Wk, bk, kp);
    sgemm_f32<true><<<gg, 256>>>(x, Wv, bv, vp);

    // 3. fused attention
    attn_kernel<<<B_ * H_, 256, sizeof(AttnSmem)>>>(corr, fi, ap);

    // 4. output projection -> d_out
    sgemm_f32<false><<<gg, 256>>>(ap, Wo, bo, out);
}

// round 13
// speedup vs baseline: 1.0599x; 1.0420x over previous
#include <cuda_runtime.h>
#include <math.h>
#include <stdint.h>

#define B_ 256
#define F_ 128
#define D_ 512
#define H_ 8
#define HD_ 64
#define KVAL_ 64

// ---------------- scratch (no allocations allowed) ----------------
__device__ float g_q[(size_t)B_ * H_ * F_ * HD_];
__device__ float g_k[(size_t)B_ * H_ * F_ * HD_];
__device__ float g_v[(size_t)B_ * H_ * F_ * HD_];
__device__ float g_attn[(size_t)B_ * F_ * D_];
__device__ float g_pv[B_];

// ---------------- kernel 1: gate scalar pv[b] ----------------
__global__ void pv_kernel(const float* __restrict__ x,
                          const float* __restrict__ W1,
                          const float* __restrict__ b1,
                          const float* __restrict__ W2,
                          const float* __restrict__ b2) {
    __shared__ float comb[2 * D_];
    __shared__ float hbuf[D_];
    __shared__ float red[256];
    int b = blockIdx.x, t = threadIdx.x;
    const float* xb = x + (size_t)b * F_ * D_;

    for (int d = t; d < D_; d += 256) {
        float sp = 0.f, sv = 0.f;
        for (int f = 0; f < F_ / 2; ++f)  sp += xb[f * D_ + d];
        for (int f = F_ / 2; f < F_; ++f) sv += xb[f * D_ + d];
        comb[d]      = sp * (2.0f / F_);
        comb[D_ + d] = sv * (2.0f / F_);
    }
    __syncthreads();

    for (int j = t; j < D_; j += 256) {
        float acc = b1[j];
        for (int i = 0; i < 2 * D_; ++i) acc += comb[i] * W1[i * D_ + j];
        hbuf[j] = acc / (1.0f + expf(-acc));
    }
    __syncthreads();

    float part = 0.f;
    for (int j = t; j < D_; j += 256) part += hbuf[j] * W2[j];
    red[t] = part;
    __syncthreads();
    for (int s = 128; s > 0; s >>= 1) {
        if (t < s) red[t] += red[t + s];
        __syncthreads();
    }
    if (t == 0) {
        float z = red[0] + b2[0];
        g_pv[b] = 1.0f / (1.0f + expf(-z));
    }
}

// ---------------- kernel 2: fp32 SIMT SGEMM, double-buffered ----------------
// C[M x 512] = A[M x 512] @ W[512 x 512] + bias.
// Tile 128x128, BK=16, 256 threads, 8x8 per thread; 2-stage smem pipeline
// (one __syncthreads per k-tile, gmem loads overlap compute).
template <bool HEAD_LAYOUT>
__global__ __launch_bounds__(256)
void sgemm_f32(const float* __restrict__ A,
               const float* __restrict__ W,
               const float* __restrict__ bias,
               float* __restrict__ C) {
    __shared__ float As[2][16][132];   // transposed A tile: As[buf][k][m]
    __shared__ float Bs[2][16][128];   // Bs[buf][k][n]

    const int m0 = blockIdx.x * 128;
    const int n0 = blockIdx.y * 128;
    const int t  = threadIdx.x;
    const int tr = t >> 4;          // 0..15 -> rows tr*8..tr*8+7
    const int tc = t & 15;          // 0..15 -> cols tc*8..tc*8+7

    // staging coordinates (fixed per thread)
    const int ar0 = t >> 2,        ac0 = (t & 3) * 4;        // j=0 A
    const int ar1 = (256 + t) >> 2, ac1 = ((256 + t) & 3) * 4; // j=1 A
    const int bk0 = t >> 5,        bc0 = (t & 31) * 4;       // j=0 B
    const int bk1 = (256 + t) >> 5, bc1 = ((256 + t) & 31) * 4; // j=1 B

    float acc[8][8] = {};
    float4 aR0, aR1, bR0, bR1;

    // prologue: load tile 0, store to buf 0
    aR0 = *(const float4*)(A + (size_t)(m0 + ar0) * 512 + ac0);
    aR1 = *(const float4*)(A + (size_t)(m0 + ar1) * 512 + ac1);
    bR0 = *(const float4*)(W + (size_t)bk0 * 512 + n0 + bc0);
    bR1 = *(const float4*)(W + (size_t)bk1 * 512 + n0 + bc1);
    As[0][ac0 + 0][ar0] = aR0.x; As[0][ac0 + 1][ar0] = aR0.y;
    As[0][ac0 + 2][ar0] = aR0.z; As[0][ac0 + 3][ar0] = aR0.w;
    As[0][ac1 + 0][ar1] = aR1.x; As[0][ac1 + 1][ar1] = aR1.y;
    As[0][ac1 + 2][ar1] = aR1.z; As[0][ac1 + 3][ar1] = aR1.w;
    *(float4*)(&Bs[0][bk0][bc0]) = bR0;
    *(float4*)(&Bs[0][bk1][bc1]) = bR1;
    __syncthreads();

    for (int kt = 0; kt < 32; ++kt) {
        const int cur = kt & 1;
        // issue gmem loads for next tile (latency overlapped with compute)
        if (kt < 31) {
            int kg = (kt + 1) * 16;
            aR0 = *(const float4*)(A + (size_t)(m0 + ar0) * 512 + kg + ac0);
            aR1 = *(const float4*)(A + (size_t)(m0 + ar1) * 512 + kg + ac1);
            bR0 = *(const float4*)(W + (size_t)(kg + bk0) * 512 + n0 + bc0);
            bR1 = *(const float4*)(W + (size_t)(kg + bk1) * 512 + n0 + bc1);
        }
#pragma unroll
        for (int k = 0; k < 16; ++k) {
            float av[8], bv[8];
            *(float4*)(av)     = *(const float4*)&As[cur][k][tr * 8];
            *(float4*)(av + 4) = *(const float4*)&As[cur][k][tr * 8 + 4];
            *(float4*)(bv)     = *(const float4*)&Bs[cur][k][tc * 8];
            *(float4*)(bv + 4) = *(const float4*)&Bs[cur][k][tc * 8 + 4];
#pragma unroll
            for (int i = 0; i < 8; ++i)
#pragma unroll
                for (int j = 0; j < 8; ++j) acc[i][j] += av[i] * bv[j];
        }
        if (kt < 31) {
            const int nxt = cur ^ 1;
            As[nxt][ac0 + 0][ar0] = aR0.x; As[nxt][ac0 + 1][ar0] = aR0.y;
            As[nxt][ac0 + 2][ar0] = aR0.z; As[nxt][ac0 + 3][ar0] = aR0.w;
            As[nxt][ac1 + 0][ar1] = aR1.x; As[nxt][ac1 + 1][ar1] = aR1.y;
            As[nxt][ac1 + 2][ar1] = aR1.z; As[nxt][ac1 + 3][ar1] = aR1.w;
            *(float4*)(&Bs[nxt][bk0][bc0]) = bR0;
            *(float4*)(&Bs[nxt][bk1][bc1]) = bR1;
        }
        __syncthreads();
    }

    // epilogue: + bias, write 8x8
    const int nb = n0 + tc * 8;
    float bv[8];
    *(float4*)(bv)     = *(const float4*)(bias + nb);
    *(float4*)(bv + 4) = *(const float4*)(bias + nb + 4);
#pragma unroll
    for (int i = 0; i < 8; ++i) {
        int m = m0 + tr * 8 + i;
        float4 r0 = make_float4(acc[i][0] + bv[0], acc[i][1] + bv[1],
                                acc[i][2] + bv[2], acc[i][3] + bv[3]);
        float4 r1 = make_float4(acc[i][4] + bv[4], acc[i][5] + bv[5],
                                acc[i][6] + bv[6], acc[i][7] + bv[7]);
        if (HEAD_LAYOUT) {
            int b  = m >> 7;          // m / F_
            int f  = m & (F_ - 1);
            int h  = nb >> 6;         // 8-col group never straddles a head
            int hd = nb & (HD_ - 1);
            size_t base = (((size_t)b * H_ + h) * F_ + f) * HD_ + hd;
            *(float4*)(C + base)     = r0;
            *(float4*)(C + base + 4) = r1;
        } else {
            *(float4*)(C + (size_t)m * 512 + nb)     = r0;
            *(float4*)(C + (size_t)m * 512 + nb + 4) = r1;
        }
    }
}

// ---------------- kernel 3: fused attention, 2 CTAs per (b, h) ----------------
// Each CTA handles 64 query rows (half) x all 128 keys.
// S padded to stride 132 (divisible by 4) so float4 row accesses are
// 16B-aligned; smem 113.5 KB -> still 2 CTAs/SM.
#define QH_ 64            // queries per CTA
#define SPAD_ (F_ + 4)    // 132: 16B-aligned rows, conflict-free patterns

struct AttnSmem {
    float Qt[HD_][QH_];       // [hd][q]   16 KB
    float Kt[HD_][F_];        // [hd][k]   32 KB
    float V[F_][HD_];         // [k][hd]   32 KB
    float S[QH_][SPAD_];      // scores    33 KB
    float fi[F_];
};

__global__ __launch_bounds__(256)
void attn_kernel(const float* __restrict__ corr,
                 const float* __restrict__ fi_g,
                 float* __restrict__ out_attn) {
    extern __shared__ char smem_raw[];
    AttnSmem& sm = *reinterpret_cast<AttnSmem*>(smem_raw);

    const int bx = blockIdx.x;
    const int bh = bx >> 1;           // (b, h)
    const int qh = bx & 1;            // query half
    const int b  = bh >> 3;
    const int h  = bh & 7;
    const int t  = threadIdx.x;

    const float4* qg = (const float4*)(g_q + ((size_t)bh * F_ + qh * QH_) * HD_);
    const float4* kg = (const float4*)(g_k + (size_t)bh * F_ * HD_);
    const float4* vg = (const float4*)(g_v + (size_t)bh * F_ * HD_);

    // ---- loads: Q half (transposed), K full (transposed), V full ----
    for (int i = t; i < QH_ * HD_ / 4; i += 256) {   // 1024 float4
        float4 q4 = qg[i];
        int f  = i >> 4;            // 16 float4 per 64-float row
        int hd = (i & 15) << 2;
        sm.Qt[hd + 0][f] = q4.x; sm.Qt[hd + 1][f] = q4.y;
        sm.Qt[hd + 2][f] = q4.z; sm.Qt[hd + 3][f] = q4.w;
    }
    for (int i = t; i < F_ * HD_ / 4; i += 256) {    // 2048 float4
        float4 k4 = kg[i];
        int f  = i >> 4;
        int hd = (i & 15) << 2;
        sm.Kt[hd + 0][f] = k4.x; sm.Kt[hd + 1][f] = k4.y;
        sm.Kt[hd + 2][f] = k4.z; sm.Kt[hd + 3][f] = k4.w;
        ((float4*)&sm.V[0][0])[i] = vg[i];
    }
    if (t < F_) sm.fi[t] = fi_g[t];
    __syncthreads();

    // ---- scores = Q K^T / 8 + prior + gate : 4q x 8k per thread ----
    {
        const int tr = t >> 4, tc = t & 15;
        const int q0 = tr * 4, k0 = tc * 8;
        float acc[4][8] = {};
#pragma unroll 4
        for (int hd = 0; hd < HD_; ++hd) {
            float4 qa = *(const float4*)&sm.Qt[hd][q0];
            float4 ka = *(const float4*)&sm.Kt[hd][k0];
            float4 kb = *(const float4*)&sm.Kt[hd][k0 + 4];
            float qv[4] = {qa.x, qa.y, qa.z, qa.w};
            float kv[8] = {ka.x, ka.y, ka.z, ka.w, kb.x, kb.y, kb.z, kb.w};
#pragma unroll
            for (int i = 0; i < 4; ++i)
#pragma unroll
                for (int j = 0; j < 8; ++j) acc[i][j] += qv[i] * kv[j];
        }
        const float pvb = g_pv[b] * 0.5f;
#pragma unroll
        for (int i = 0; i < 4; ++i) {
            int fl = q0 + i;                 // local row
            int fq = qh * QH_ + fl;          // global query index
            float fiq = sm.fi[fq];
            bool qlow = fq < (F_ / 2);
#pragma unroll
            for (int j = 0; j < 8; ++j) {
                int kk = k0 + j;
                float sc = acc[i][j] * 0.125f;
                sc += corr[fq * F_ + kk] * (fiq * sm.fi[kk]);
                if (qlow != (kk < (F_ / 2))) sc += pvb;
                sm.S[fl][kk] = sc;
            }
        }
    }
    __syncthreads();

    // ---- per-row exact 64th-largest threshold + softmax ----
    // 8 warps x 8 rows; 2 groups of 4 rows; counts for 4 rows packed into
    // one u32 (byte sums <= 128, no carry) -> 1 REDUX per radix bit.
    {
        const int warp = t >> 5, lane = t & 31;
#pragma unroll
        for (int grp = 0; grp < 2; ++grp) {
            int row0 = warp * 8 + grp * 4;
            float vals[4][4];
            unsigned keys[4][4];
#pragma unroll
            for (int rr = 0; rr < 4; ++rr)
#pragma unroll
                for (int i = 0; i < 4; ++i) {
                    float v = sm.S[row0 + rr][lane + 32 * i];
                    vals[rr][i] = v;
                    unsigned u = __float_as_uint(v);
                    keys[rr][i] = (u & 0x80000000u) ? ~u : (u | 0x80000000u);
                }
            unsigned prefix[4] = {0, 0, 0, 0};
            int r[4] = {KVAL_ - 1, KVAL_ - 1, KVAL_ - 1, KVAL_ - 1};
#pragma unroll
            for (int bit = 31; bit >= 0; --bit) {
                unsigned loc4 = 0;
#pragma unroll
                for (int rr = 0; rr < 4; ++rr) {
                    unsigned test = prefix[rr] | (1u << bit);
                    unsigned loc = 0;
#pragma unroll
                    for (int i = 0; i < 4; ++i)
                        loc += ((keys[rr][i] >> bit) == (test >> bit));
                    loc4 |= loc << (8 * rr);
                }
                unsigned cnt4 = __reduce_add_sync(0xffffffffu, loc4);
#pragma unroll
                for (int rr = 0; rr < 4; ++rr) {
                    int cnt = (cnt4 >> (8 * rr)) & 0xFF;
                    unsigned test = prefix[rr] | (1u << bit);
                    if (cnt > r[rr]) prefix[rr] = test;
                    else             r[rr] -= cnt;
                }
            }
#pragma unroll
            for (int rr = 0; rr < 4; ++rr) {
                float mx = fmaxf(fmaxf(vals[rr][0], vals[rr][1]),
                                 fmaxf(vals[rr][2], vals[rr][3]));
#pragma unroll
                for (int o = 16; o > 0; o >>= 1)
                    mx = fmaxf(mx, __shfl_xor_sync(0xffffffffu, mx, o));
                float e[4];
                float sum = 0.f;
#pragma unroll
                for (int i = 0; i < 4; ++i) {
                    e[i] = (keys[rr][i] >= prefix[rr]) ? __expf(vals[rr][i] - mx) : 0.f;
                    sum += e[i];
                }
#pragma unroll
                for (int o = 16; o > 0; o >>= 1)
                    sum += __shfl_xor_sync(0xffffffffu, sum, o);
                float inv = 1.0f / sum;
#pragma unroll
                for (int i = 0; i < 4; ++i)
                    sm.S[row0 + rr][lane + 32 * i] = e[i] * inv;
            }
        }
    }
    __syncthreads();

    // ---- out = attn @ V : 2 q x 8 d per thread, k in chunks of 4 ----
    {
        const int qg2 = t >> 3;           // 0..31 -> rows qg2*2, qg2*2+1
        const int d0  = (t & 7) * 8;      // 0..56
        const int r0  = qg2 * 2;
        float acc2[2][8] = {};
        for (int kk = 0; kk < F_; kk += 4) {
            float4 s0 = *(const float4*)&sm.S[r0][kk];
            float4 s1 = *(const float4*)&sm.S[r0 + 1][kk];
            float sv0[4] = {s0.x, s0.y, s0.z, s0.w};
            float sv1[4] = {s1.x, s1.y, s1.z, s1.w};
#pragma unroll
            for (int e = 0; e < 4; ++e) {
                float4 va = *(const float4*)&sm.V[kk + e][d0];
                float4 vb = *(const float4*)&sm.V[kk + e][d0 + 4];
                float vv[8] = {va.x, va.y, va.z, va.w, vb.x, vb.y, vb.z, vb.w};
#pragma unroll
                for (int j = 0; j < 8; ++j) {
                    acc2[0][j] += sv0[e] * vv[j];
                    acc2[1][j] += sv1[e] * vv[j];
                }
            }
        }
#pragma unroll
        for (int i = 0; i < 2; ++i) {
            int fq = qh * QH_ + r0 + i;
            float* og = out_attn + ((size_t)b * F_ + fq) * D_ + h * HD_ + d0;
            *(float4*)(og)     = make_float4(acc2[i][0], acc2[i][1], acc2[i][2], acc2[i][3]);
            *(float4*)(og + 4) = make_float4(acc2[i][4], acc2[i][5], acc2[i][6], acc2[i][7]);
        }
    }
}

// ---------------- host launcher ----------------
extern "C" void kernel_launch(void* const* d_in, const int* in_sizes, int n_in,
                              void* d_out, int out_size) {
    const float* x    = (const float*)d_in[0];
    const float* Wq   = (const float*)d_in[1];
    const float* bq   = (const float*)d_in[2];
    const float* Wk   = (const float*)d_in[3];
    const float* bk   = (const float*)d_in[4];
    const float* Wv   = (const float*)d_in[5];
    const float* bv   = (const float*)d_in[6];
    const float* Wo   = (const float*)d_in[7];
    const float* bo   = (const float*)d_in[8];
    const float* corr = (const float*)d_in[9];
    const float* fi   = (const float*)d_in[10];
    const float* W1   = (const float*)d_in[11];
    const float* b1   = (const float*)d_in[12];
    const float* W2   = (const float*)d_in[13];
    const float* b2   = (const float*)d_in[14];
    float* out = (float*)d_out;

    float *qp, *kp, *vp, *ap;
    cudaGetSymbolAddress((void**)&qp, g_q);
    cudaGetSymbolAddress((void**)&kp, g_k);
    cudaGetSymbolAddress((void**)&vp, g_v);
    cudaGetSymbolAddress((void**)&ap, g_attn);

    cudaFuncSetAttribute(attn_kernel,
                         cudaFuncAttributeMaxDynamicSharedMemorySize,
                         (int)sizeof(AttnSmem));

    // 1. gate scalar
    pv_kernel<<<B_, 256>>>(x, W1, b1, W2, b2);

    // 2. Q/K/V projections (head-major outputs), pure fp32
    dim3 gg(256, 4);   // M/128 = 32768/128, N/128 = 4
    sgemm_f32<true><<<gg, 256>>>(x, Wq, bq, qp);
    sgemm_f32<true><<<gg, 256>>>(x, Wk, bk, kp);
    sgemm_f32<true><<<gg, 256>>>(x, Wv, bv, vp);

    // 3. fused attention: 2 CTAs per (b, h)
    attn_kernel<<<B_ * H_ * 2, 256, sizeof(AttnSmem)>>>(corr, fi, ap);

    // 4. output projection -> d_out
    sgemm_f32<false><<<gg, 256>>>(ap, Wo, bo, out);
}